// round 4
// baseline (speedup 1.0000x reference)
#include <cuda_runtime.h>
#include <math.h>

#define A_N   16
#define H     128
#define IN_D  128
#define NA    32
#define NACT  14
#define TAUF  0.5f
#define BZ    16384
#define T_N   15
#define G3    384   // 3*H

// ---- scratch layout (floats) ----
// U = BZ*H = 2097152, V = BZ*G3 = 6291456
// x1:U gi:V gh:V hrnn:U gsf:V gnf:V gsb:V gnb:V ghf:V ghb:V hf:U hb:U
// yf:15U yb:15U hard:BZ*15 q:BZ*32 k:BZ*32 agg:U
static __device__ float g_scratch[125026304];

__device__ __forceinline__ float sigf(float x){ return 1.0f/(1.0f+expf(-x)); }

// ============================================================
// SGEMM: C[m,n] = sum_k A[m*lda+k] * W[n*ldw + wofs + k] (+bias[n]) (+relu)
// tile 128x128, BK=8, 256 threads, 8x8 per thread. M must be mult of 128.
// EPI: 0=none, 1=bias, 2=bias+relu
// ============================================================
template<int EPI>
__global__ void sgemm(const float* __restrict__ Amat, int lda,
                      const float* __restrict__ W, int ldw, int wofs,
                      const float* __restrict__ bias,
                      float* __restrict__ C, int N, int K)
{
    __shared__ float As[8][128];
    __shared__ float Bs[8][128];
    const int tid = threadIdx.x;
    const int rowBase = blockIdx.y * 128;
    const int colBase = blockIdx.x * 128;
    const int lr = tid >> 1;            // 0..127
    const int lc = (tid & 1) * 4;       // 0 or 4

    float acc[8][8];
#pragma unroll
    for (int i = 0; i < 8; i++)
#pragma unroll
        for (int j = 0; j < 8; j++) acc[i][j] = 0.0f;

    const int ty = tid >> 4;   // 0..15
    const int tx = tid & 15;   // 0..15

    for (int k0 = 0; k0 < K; k0 += 8) {
        float4 av = *reinterpret_cast<const float4*>(
            Amat + (size_t)(rowBase + lr) * lda + k0 + lc);
        int n = colBase + lr;
        float4 bv = make_float4(0.f, 0.f, 0.f, 0.f);
        if (n < N)
            bv = *reinterpret_cast<const float4*>(
                W + (size_t)n * ldw + wofs + k0 + lc);

        As[lc + 0][lr] = av.x; As[lc + 1][lr] = av.y;
        As[lc + 2][lr] = av.z; As[lc + 3][lr] = av.w;
        Bs[lc + 0][lr] = bv.x; Bs[lc + 1][lr] = bv.y;
        Bs[lc + 2][lr] = bv.z; Bs[lc + 3][lr] = bv.w;
        __syncthreads();

#pragma unroll
        for (int kk = 0; kk < 8; kk++) {
            float a[8], b[8];
            *reinterpret_cast<float4*>(a)     = *reinterpret_cast<const float4*>(&As[kk][ty*8]);
            *reinterpret_cast<float4*>(a + 4) = *reinterpret_cast<const float4*>(&As[kk][ty*8+4]);
            *reinterpret_cast<float4*>(b)     = *reinterpret_cast<const float4*>(&Bs[kk][tx*8]);
            *reinterpret_cast<float4*>(b + 4) = *reinterpret_cast<const float4*>(&Bs[kk][tx*8+4]);
#pragma unroll
            for (int i = 0; i < 8; i++)
#pragma unroll
                for (int j = 0; j < 8; j++)
                    acc[i][j] = fmaf(a[i], b[j], acc[i][j]);
        }
        __syncthreads();
    }

#pragma unroll
    for (int i = 0; i < 8; i++) {
        int m = rowBase + ty * 8 + i;
#pragma unroll
        for (int j = 0; j < 8; j++) {
            int n = colBase + tx * 8 + j;
            if (n < N) {
                float v = acc[i][j];
                if (EPI >= 1) v += bias[n];
                if (EPI == 2) v = fmaxf(v, 0.0f);
                C[(size_t)m * N + n] = v;
            }
        }
    }
}

// ============================================================
// Central GRU combine: h' = (1-z)*n + z*h   (writes scratch + d_out tail)
// ============================================================
__global__ void gru_central(const float* __restrict__ gi, const float* __restrict__ gh,
                            const float* __restrict__ hprev,
                            float* __restrict__ hrnn, float* __restrict__ out_h)
{
    int e = blockIdx.x * 256 + threadIdx.x;     // < BZ*H
    int row = e >> 7, hh = e & 127;
    size_t base = (size_t)row * G3;
    float r = sigf(gi[base + hh]        + gh[base + hh]);
    float z = sigf(gi[base + 128 + hh]  + gh[base + 128 + hh]);
    float n = tanhf(gi[base + 256 + hh] + r * gh[base + 256 + hh]);
    float hv = (1.0f - z) * n + z * hprev[e];
    hrnn[e]  = hv;
    out_h[e] = hv;
}

// ============================================================
// Bi-GRU step (both directions via blockIdx.y).
// gi[t,row] = gs[row] + gn[neighbor_row(t)]  (gather fused here)
// gh already contains bhh (added in GEMM epilogue).
// fwd processes t=s, bwd processes t=14-s.
// ============================================================
__global__ void gru_step(const float* __restrict__ gs_f, const float* __restrict__ gn_f,
                         const float* __restrict__ gh_f,
                         const float* __restrict__ gs_b, const float* __restrict__ gn_b,
                         const float* __restrict__ gh_b,
                         float* __restrict__ hf, float* __restrict__ hb,
                         float* __restrict__ yf, float* __restrict__ yb, int s)
{
    int dir = blockIdx.y;
    int e = blockIdx.x * 256 + threadIdx.x;     // < BZ*H
    int row = e >> 7, hh = e & 127;
    int b = row >> 4, i = row & 15;
    int t = dir ? (T_N - 1 - s) : s;
    int j = t + (t >= i);                        // IDX[i][t]
    size_t rb = (size_t)row * G3;
    size_t nb = (size_t)((b << 4) | j) * G3;

    const float* gs = dir ? gs_b : gs_f;
    const float* gn = dir ? gn_b : gn_f;
    const float* gh = dir ? gh_b : gh_f;
    float* hc = dir ? hb : hf;
    float* y  = dir ? yb : yf;

    float gir = gs[rb + hh]       + gn[nb + hh];
    float giz = gs[rb + 128 + hh] + gn[nb + 128 + hh];
    float gin = gs[rb + 256 + hh] + gn[nb + 256 + hh];
    float r = sigf(gir + gh[rb + hh]);
    float z = sigf(giz + gh[rb + 128 + hh]);
    float n = tanhf(gin + r * gh[rb + 256 + hh]);
    float hv = (1.0f - z) * n + z * hc[e];
    hc[e] = hv;
    y[(size_t)t * BZ * H + e] = hv;
}

// ============================================================
// logits + gumbel softmax -> hard_w.  One warp per (row, t) pair.
// hard_w = sigmoid(((l1+g1)-(l0+g0))/TAU)
// ============================================================
__global__ void gumbel_kernel(const float* __restrict__ yf, const float* __restrict__ yb,
                              const float* __restrict__ Wc, const float* __restrict__ bc,
                              const float* __restrict__ gu, float* __restrict__ hard)
{
    __shared__ float wc[512];
    int tid = threadIdx.x;
    for (int x = tid; x < 512; x += 256) wc[x] = Wc[x];
    __syncthreads();

    int warp = tid >> 5, lane = tid & 31;
    int p = blockIdx.x * 8 + warp;               // < BZ*15 = 245760
    if (p >= BZ * T_N) return;
    int row = p / 15, t = p % 15;
    const float* f  = yf + (size_t)t * BZ * H + (size_t)row * H;
    const float* bk = yb + (size_t)t * BZ * H + (size_t)row * H;

    float s0 = 0.f, s1 = 0.f;
#pragma unroll
    for (int c = 0; c < 4; c++) {
        int hh = lane + 32 * c;
        float vf = f[hh], vb = bk[hh];
        s0 += vf * wc[hh]       + vb * wc[128 + hh];
        s1 += vf * wc[256 + hh] + vb * wc[384 + hh];
    }
#pragma unroll
    for (int o = 16; o; o >>= 1) {
        s0 += __shfl_xor_sync(0xFFFFFFFFu, s0, o);
        s1 += __shfl_xor_sync(0xFFFFFFFFu, s1, o);
    }
    if (lane == 0) {
        float l0 = s0 + bc[0], l1 = s1 + bc[1];
        float u0 = gu[2 * (size_t)p], u1 = gu[2 * (size_t)p + 1];
        float g0 = -logf(-logf(u0 + 1e-10f) + 1e-10f);
        float g1 = -logf(-logf(u1 + 1e-10f) + 1e-10f);
        hard[p] = sigf(((l1 + g1) - (l0 + g0)) / TAUF);
    }
}

// ============================================================
// attention scores + softmax + aggregation.  One warp per (b, i) row.
// ============================================================
__global__ void attn_agg(const float* __restrict__ q, const float* __restrict__ k,
                         const float* __restrict__ hard, const float* __restrict__ hrnn,
                         float* __restrict__ agg)
{
    int warp = threadIdx.x >> 5, lane = threadIdx.x & 31;
    int row = blockIdx.x * 8 + warp;             // < BZ
    int b = row >> 4, i = row & 15;

    float sc = -1e30f, hw = 0.f;
    if (lane < 15) {
        int j = lane + (lane >= i);
        int nrow = (b << 4) | j;
        hw = hard[(size_t)row * 15 + lane];
        const float* qr = q + (size_t)row * NA;
        const float* kr = k + (size_t)nrow * NA;
        float dot = 0.f;
#pragma unroll
        for (int d = 0; d < NA; d++) dot += qr[d] * kr[d];
        sc = dot * hw * 0.17677669529663687f;    // 1/sqrt(32)
    }
    float mx = sc;
#pragma unroll
    for (int o = 16; o; o >>= 1) mx = fmaxf(mx, __shfl_xor_sync(0xFFFFFFFFu, mx, o));
    float ev = (lane < 15) ? expf(sc - mx) : 0.f;
    float se = ev;
#pragma unroll
    for (int o = 16; o; o >>= 1) se += __shfl_xor_sync(0xFFFFFFFFu, se, o);
    float wgt = (lane < 15) ? hw * (ev / se) : 0.f;

#pragma unroll
    for (int c = 0; c < 4; c++) {
        float acc = 0.f;
#pragma unroll
        for (int m = 0; m < 15; m++) {
            float wm = __shfl_sync(0xFFFFFFFFu, wgt, m);
            int jm = m + (m >= i);
            acc += wm * hrnn[(size_t)((b << 4) | jm) * H + c * 32 + lane];
        }
        agg[(size_t)row * H + c * 32 + lane] = acc;
    }
}

// ============================================================
// out = [hrnn | agg] @ W2^T + b2   (N=14, K=256)
// ============================================================
__global__ void out_kernel(const float* __restrict__ hrnn, const float* __restrict__ agg,
                           const float* __restrict__ W2, const float* __restrict__ b2,
                           float* __restrict__ out)
{
    __shared__ float w2s[NACT * 256];
    int tid = threadIdx.x;
    for (int x = tid; x < NACT * 256; x += 256) w2s[x] = W2[x];
    __syncthreads();

    int g = blockIdx.x * 256 + tid;
    if (g >= BZ * NACT) return;
    int row = g / NACT, n = g % NACT;
    const float* hr = hrnn + (size_t)row * H;
    const float* ag = agg  + (size_t)row * H;
    float acc = b2[n];
#pragma unroll 4
    for (int kk = 0; kk < 128; kk++) acc += hr[kk] * w2s[n * 256 + kk];
#pragma unroll 4
    for (int kk = 0; kk < 128; kk++) acc += ag[kk] * w2s[n * 256 + 128 + kk];
    out[g] = acc;
}

// ============================================================
extern "C" void kernel_launch(void* const* d_in, const int* in_sizes, int n_in,
                              void* d_out, int out_size)
{
    const float* inputs = (const float*)d_in[0];
    const float* hidden = (const float*)d_in[1];
    const float* gu     = (const float*)d_in[2];
    const float* W1     = (const float*)d_in[3];
    const float* b1     = (const float*)d_in[4];
    const float* Wih_c  = (const float*)d_in[5];
    const float* Whh_c  = (const float*)d_in[6];
    const float* bih_c  = (const float*)d_in[7];
    const float* bhh_c  = (const float*)d_in[8];
    const float* Wih_f  = (const float*)d_in[9];
    const float* Whh_f  = (const float*)d_in[10];
    const float* bih_f  = (const float*)d_in[11];
    const float* bhh_f  = (const float*)d_in[12];
    const float* Wih_b  = (const float*)d_in[13];
    const float* Whh_b  = (const float*)d_in[14];
    const float* bih_b  = (const float*)d_in[15];
    const float* bhh_b  = (const float*)d_in[16];
    const float* Wc     = (const float*)d_in[17];
    const float* bc     = (const float*)d_in[18];
    const float* Wq     = (const float*)d_in[19];
    const float* Wk     = (const float*)d_in[20];
    const float* W2     = (const float*)d_in[21];
    const float* b2     = (const float*)d_in[22];

    float* S = nullptr;
    cudaGetSymbolAddress((void**)&S, g_scratch);

    const size_t U = (size_t)BZ * H;
    const size_t V = (size_t)BZ * G3;
    float* x1   = S;
    float* gi   = x1 + U;
    float* gh   = gi + V;
    float* hrnn = gh + V;
    float* gsf  = hrnn + U;
    float* gnf  = gsf + V;
    float* gsb  = gnf + V;
    float* gnb  = gsb + V;
    float* ghf  = gnb + V;
    float* ghb  = ghf + V;
    float* hf   = ghb + V;
    float* hb   = hf + U;
    float* yf   = hb + U;
    float* yb   = yf + 15 * U;
    float* hard = yb + 15 * U;
    float* qv   = hard + (size_t)BZ * 15;
    float* kv   = qv + (size_t)BZ * 32;
    float* agg  = kv + (size_t)BZ * 32;

    float* out   = (float*)d_out;
    float* out_h = out + (size_t)BZ * NACT;

    dim3 blk(256);
    auto grd = [](int N) { return dim3((N + 127) / 128, BZ / 128); };

    cudaMemsetAsync(hf, 0, U * sizeof(float));
    cudaMemsetAsync(hb, 0, U * sizeof(float));

    // x1 = relu(inputs @ W1^T + b1)
    sgemm<2><<<grd(128), blk>>>(inputs, IN_D, W1, IN_D, 0, b1, x1, 128, IN_D);
    // central GRU gates
    sgemm<1><<<grd(G3), blk>>>(x1,     H, Wih_c, H, 0, bih_c, gi, G3, H);
    sgemm<1><<<grd(G3), blk>>>(hidden, H, Whh_c, H, 0, bhh_c, gh, G3, H);
    gru_central<<<BZ * H / 256, blk>>>(gi, gh, hidden, hrnn, out_h);

    // factored input-gate precompute for bi-GRU (self part + neighbor part)
    sgemm<1><<<grd(G3), blk>>>(hrnn, H, Wih_f, 256, 0,   bih_f,  gsf, G3, H);
    sgemm<0><<<grd(G3), blk>>>(hrnn, H, Wih_f, 256, 128, nullptr, gnf, G3, H);
    sgemm<1><<<grd(G3), blk>>>(hrnn, H, Wih_b, 256, 0,   bih_b,  gsb, G3, H);
    sgemm<0><<<grd(G3), blk>>>(hrnn, H, Wih_b, 256, 128, nullptr, gnb, G3, H);

    // 15 sequential recurrence steps, both directions
    for (int s = 0; s < T_N; s++) {
        sgemm<1><<<grd(G3), blk>>>(hf, H, Whh_f, H, 0, bhh_f, ghf, G3, H);
        sgemm<1><<<grd(G3), blk>>>(hb, H, Whh_b, H, 0, bhh_b, ghb, G3, H);
        dim3 gs2(BZ * H / 256, 2);
        gru_step<<<gs2, blk>>>(gsf, gnf, ghf, gsb, gnb, ghb, hf, hb, yf, yb, s);
    }

    // gumbel hard weights
    gumbel_kernel<<<(BZ * T_N + 7) / 8, blk>>>(yf, yb, Wc, bc, gu, hard);

    // q, k projections
    sgemm<0><<<grd(32), blk>>>(hrnn, H, Wq, H, 0, nullptr, qv, 32, H);
    sgemm<0><<<grd(32), blk>>>(hrnn, H, Wk, H, 0, nullptr, kv, 32, H);

    // attention + aggregation
    attn_agg<<<BZ / 8, blk>>>(qv, kv, hard, hrnn, agg);

    // output head
    out_kernel<<<(BZ * NACT + 255) / 256, blk>>>(hrnn, agg, W2, b2, out);
}

// round 6
// speedup vs baseline: 1.3154x; 1.3154x over previous
#include <cuda_runtime.h>
#include <math.h>

#define A_N   16
#define H     128
#define IN_D  128
#define NA    32
#define NACT  14
#define TAUF  0.5f
#define BZ    16384
#define T_N   15
#define G3    384   // 3*H
#define RT    64    // rows per recurrence tile

static __device__ float g_scratch[125026304];

__device__ __forceinline__ float sigf(float x){ return 1.0f/(1.0f+expf(-x)); }

// ============================================================
// Generic SGEMM: C[m,n] = sum_k A[m*lda+k] * W[n*ldw + wofs + k] (+bias) (+relu)
// 128x128 tile, BK=8, 256 threads, 8x8 microtile.
// ============================================================
template<int EPI>
__global__ void sgemm(const float* __restrict__ Amat, int lda,
                      const float* __restrict__ W, int ldw, int wofs,
                      const float* __restrict__ bias,
                      float* __restrict__ C, int N, int K)
{
    __shared__ float As[8][128];
    __shared__ float Bs[8][128];
    const int tid = threadIdx.x;
    const int rowBase = blockIdx.y * 128;
    const int colBase = blockIdx.x * 128;
    const int lr = tid >> 1;
    const int lc = (tid & 1) * 4;

    float acc[8][8];
#pragma unroll
    for (int i = 0; i < 8; i++)
#pragma unroll
        for (int j = 0; j < 8; j++) acc[i][j] = 0.0f;

    const int ty = tid >> 4;
    const int tx = tid & 15;

    for (int k0 = 0; k0 < K; k0 += 8) {
        float4 av = *reinterpret_cast<const float4*>(
            Amat + (size_t)(rowBase + lr) * lda + k0 + lc);
        int n = colBase + lr;
        float4 bv = make_float4(0.f, 0.f, 0.f, 0.f);
        if (n < N)
            bv = *reinterpret_cast<const float4*>(
                W + (size_t)n * ldw + wofs + k0 + lc);

        As[lc + 0][lr] = av.x; As[lc + 1][lr] = av.y;
        As[lc + 2][lr] = av.z; As[lc + 3][lr] = av.w;
        Bs[lc + 0][lr] = bv.x; Bs[lc + 1][lr] = bv.y;
        Bs[lc + 2][lr] = bv.z; Bs[lc + 3][lr] = bv.w;
        __syncthreads();

#pragma unroll
        for (int kk = 0; kk < 8; kk++) {
            float a[8], b[8];
            *reinterpret_cast<float4*>(a)     = *reinterpret_cast<const float4*>(&As[kk][ty*8]);
            *reinterpret_cast<float4*>(a + 4) = *reinterpret_cast<const float4*>(&As[kk][ty*8+4]);
            *reinterpret_cast<float4*>(b)     = *reinterpret_cast<const float4*>(&Bs[kk][tx*8]);
            *reinterpret_cast<float4*>(b + 4) = *reinterpret_cast<const float4*>(&Bs[kk][tx*8+4]);
#pragma unroll
            for (int i = 0; i < 8; i++)
#pragma unroll
                for (int j = 0; j < 8; j++)
                    acc[i][j] = fmaf(a[i], b[j], acc[i][j]);
        }
        __syncthreads();
    }

#pragma unroll
    for (int i = 0; i < 8; i++) {
        int m = rowBase + ty * 8 + i;
#pragma unroll
        for (int j = 0; j < 8; j++) {
            int n = colBase + tx * 8 + j;
            if (n < N) {
                float v = acc[i][j];
                if (EPI >= 1) v += bias[n];
                if (EPI == 2) v = fmaxf(v, 0.0f);
                C[(size_t)m * N + n] = v;
            }
        }
    }
}

// ============================================================
// Packed input-gate GEMM for the bi-GRU: writes gall[BZ][1536] =
// [ gsf | gnf | gsb | gnb ].  N-tile T (0..11) selects the weight slice.
// ============================================================
__global__ void sgemm_ih(const float* __restrict__ Amat,
                         const float* __restrict__ Wih_f, const float* __restrict__ bih_f,
                         const float* __restrict__ Wih_b, const float* __restrict__ bih_b,
                         float* __restrict__ C)
{
    __shared__ float As[8][128];
    __shared__ float Bs[8][128];
    const int tid = threadIdx.x;
    const int rowBase = blockIdx.y * 128;
    const int T = blockIdx.x;                 // 0..11
    const int colBase = T * 128;
    const int midx = T / 3;                   // 0:gsf 1:gnf 2:gsb 3:gnb
    const float* W = (midx < 2) ? Wih_f : Wih_b;
    const int wofs = (midx & 1) ? 128 : 0;
    const float* bias = (midx == 0) ? bih_f : (midx == 2) ? bih_b : nullptr;
    const int nlBase = colBase - midx * 384;  // local n base within slice (0/128/256)

    const int lr = tid >> 1;
    const int lc = (tid & 1) * 4;

    float acc[8][8];
#pragma unroll
    for (int i = 0; i < 8; i++)
#pragma unroll
        for (int j = 0; j < 8; j++) acc[i][j] = 0.0f;

    const int ty = tid >> 4;
    const int tx = tid & 15;

    for (int k0 = 0; k0 < 128; k0 += 8) {
        float4 av = *reinterpret_cast<const float4*>(
            Amat + (size_t)(rowBase + lr) * 128 + k0 + lc);
        float4 bv = *reinterpret_cast<const float4*>(
            W + (size_t)(nlBase + lr) * 256 + wofs + k0 + lc);

        As[lc + 0][lr] = av.x; As[lc + 1][lr] = av.y;
        As[lc + 2][lr] = av.z; As[lc + 3][lr] = av.w;
        Bs[lc + 0][lr] = bv.x; Bs[lc + 1][lr] = bv.y;
        Bs[lc + 2][lr] = bv.z; Bs[lc + 3][lr] = bv.w;
        __syncthreads();

#pragma unroll
        for (int kk = 0; kk < 8; kk++) {
            float a[8], b[8];
            *reinterpret_cast<float4*>(a)     = *reinterpret_cast<const float4*>(&As[kk][ty*8]);
            *reinterpret_cast<float4*>(a + 4) = *reinterpret_cast<const float4*>(&As[kk][ty*8+4]);
            *reinterpret_cast<float4*>(b)     = *reinterpret_cast<const float4*>(&Bs[kk][tx*8]);
            *reinterpret_cast<float4*>(b + 4) = *reinterpret_cast<const float4*>(&Bs[kk][tx*8+4]);
#pragma unroll
            for (int i = 0; i < 8; i++)
#pragma unroll
                for (int j = 0; j < 8; j++)
                    acc[i][j] = fmaf(a[i], b[j], acc[i][j]);
        }
        __syncthreads();
    }

#pragma unroll
    for (int i = 0; i < 8; i++) {
        int m = rowBase + ty * 8 + i;
#pragma unroll
        for (int j = 0; j < 8; j++) {
            int n = colBase + tx * 8 + j;
            float v = acc[i][j];
            if (bias) v += bias[nlBase + tx * 8 + j];   // FIXED: local n within slice
            C[(size_t)m * 1536 + n] = v;
        }
    }
}

// ============================================================
// Central GRU combine
// ============================================================
__global__ void gru_central(const float* __restrict__ gi, const float* __restrict__ gh,
                            const float* __restrict__ hprev,
                            float* __restrict__ hrnn, float* __restrict__ out_h)
{
    int e = blockIdx.x * 256 + threadIdx.x;
    int row = e >> 7, hh = e & 127;
    size_t base = (size_t)row * G3;
    float r = sigf(gi[base + hh]        + gh[base + hh]);
    float z = sigf(gi[base + 128 + hh]  + gh[base + 128 + hh]);
    float n = tanhf(gi[base + 256 + hh] + r * gh[base + 256 + hh]);
    float hv = (1.0f - z) * n + z * hprev[e];
    hrnn[e]  = hv;
    out_h[e] = hv;
}

// ============================================================
// Fused persistent bi-GRU recurrence.
// Block = 64 rows of one direction, all 15 steps.
// smem: Wt [128][384] (Whh transposed, float4-col XOR-swizzled by (k>>2)&7)
//       hT [128][64]  (h transposed, float-col XOR-swizzled by 4*((k>>3)&7))
// Also emits per-(row,t) partial Wc logits (y tensors never materialized).
// ============================================================
__global__ __launch_bounds__(256, 1)
void recur_fused(const float* __restrict__ gall,
                 const float* __restrict__ Whh_f, const float* __restrict__ bhh_f,
                 const float* __restrict__ Whh_b, const float* __restrict__ bhh_b,
                 const float* __restrict__ Wc,
                 float2* __restrict__ lpf, float2* __restrict__ lpb)
{
    extern __shared__ float sm[];
    float*  Wt  = sm;                       // 49152 floats
    float*  hT  = sm + 128 * 384;           // 8192 floats
    float4* Wt4 = reinterpret_cast<float4*>(Wt);
    float4* hT4 = reinterpret_cast<float4*>(hT);

    const int tid = threadIdx.x;
    const int rg  = tid >> 4;               // 0..15 -> rows 4*rg..+3
    const int cg  = tid & 15;               // 0..15 -> hh 8*cg..+7
    const int dir = blockIdx.x >> 8;        // 0 fwd, 1 bwd
    const int tb  = (blockIdx.x & 255) * RT;
    const int hh0 = cg * 8;

    const float* Whh = dir ? Whh_b : Whh_f;
    const float* bhh = dir ? bhh_b : bhh_f;
    float2* lp = dir ? lpb : lpf;
    const int gofs = dir ? 768 : 0;         // offset of [gs|gn] pair in gall row

    // ---- load Whh transposed + swizzled ----
    for (int q = tid; q < 384 * 32; q += 256) {
        int n  = q >> 5;
        int k0 = (q & 31) * 4;
        float4 v = *reinterpret_cast<const float4*>(Whh + (size_t)n * 128 + k0);
        int s3   = (k0 >> 2) & 7;
        int colf = ((n >> 2) ^ s3) * 4 + (n & 3);
        Wt[(k0 + 0) * 384 + colf] = v.x;
        Wt[(k0 + 1) * 384 + colf] = v.y;
        Wt[(k0 + 2) * 384 + colf] = v.z;
        Wt[(k0 + 3) * 384 + colf] = v.w;
    }
    for (int q = tid; q < 128 * 64; q += 256) hT[q] = 0.0f;

    // Wc slice for this thread's hh range (registers)
    float wc0[8], wc1[8];
#pragma unroll
    for (int e = 0; e < 8; e++) {
        wc0[e] = Wc[dir * 128 + hh0 + e];
        wc1[e] = Wc[256 + dir * 128 + hh0 + e];
    }

    float hprev[4][8];
#pragma unroll
    for (int i = 0; i < 4; i++)
#pragma unroll
        for (int e = 0; e < 8; e++) hprev[i][e] = 0.0f;

    __syncthreads();

    for (int s = 0; s < T_N; s++) {
        const int t = dir ? (T_N - 1 - s) : s;

        // acc = bhh (broadcast over rows)
        float acc[3][4][8];
#pragma unroll
        for (int g = 0; g < 3; g++) {
            float4 b0 = *reinterpret_cast<const float4*>(bhh + g * 128 + hh0);
            float4 b1 = *reinterpret_cast<const float4*>(bhh + g * 128 + hh0 + 4);
#pragma unroll
            for (int i = 0; i < 4; i++) {
                acc[g][i][0] = b0.x; acc[g][i][1] = b0.y; acc[g][i][2] = b0.z; acc[g][i][3] = b0.w;
                acc[g][i][4] = b1.x; acc[g][i][5] = b1.y; acc[g][i][6] = b1.z; acc[g][i][7] = b1.w;
            }
        }

        // ---- GEMM: gh += h @ Whh^T  (from smem) ----
#pragma unroll 2
        for (int k = 0; k < 128; k++) {
            float4 a4 = hT4[k * 16 + (rg ^ ((k >> 3) & 7))];
            float a[4] = {a4.x, a4.y, a4.z, a4.w};
            int sw = (k >> 2) & 7;
#pragma unroll
            for (int g = 0; g < 3; g++) {
                float4 w0 = Wt4[k * 96 + ((2 * cg     + 32 * g) ^ sw)];
                float4 w1 = Wt4[k * 96 + ((2 * cg + 1 + 32 * g) ^ sw)];
#pragma unroll
                for (int i = 0; i < 4; i++) {
                    acc[g][i][0] = fmaf(a[i], w0.x, acc[g][i][0]);
                    acc[g][i][1] = fmaf(a[i], w0.y, acc[g][i][1]);
                    acc[g][i][2] = fmaf(a[i], w0.z, acc[g][i][2]);
                    acc[g][i][3] = fmaf(a[i], w0.w, acc[g][i][3]);
                    acc[g][i][4] = fmaf(a[i], w1.x, acc[g][i][4]);
                    acc[g][i][5] = fmaf(a[i], w1.y, acc[g][i][5]);
                    acc[g][i][6] = fmaf(a[i], w1.z, acc[g][i][6]);
                    acc[g][i][7] = fmaf(a[i], w1.w, acc[g][i][7]);
                }
            }
        }
        __syncthreads();   // all hT reads complete before overwrite

        // ---- fused GRU elementwise + partial logits ----
        float p0[4], p1[4];
#pragma unroll
        for (int i = 0; i < 4; i++) { p0[i] = 0.0f; p1[i] = 0.0f; }

#pragma unroll
        for (int i = 0; i < 4; i++) {
            int row = tb + rg * 4 + i;
            int bb = row >> 4, ii = row & 15;
            int jn = t + (t >= ii);
            int nrow = (bb << 4) | jn;
            const float* gsr = gall + (size_t)row  * 1536 + gofs;
            const float* gnr = gall + (size_t)nrow * 1536 + gofs + 384;

            float gi[3][8];
#pragma unroll
            for (int g = 0; g < 3; g++) {
                float4 sa = *reinterpret_cast<const float4*>(gsr + g * 128 + hh0);
                float4 sb = *reinterpret_cast<const float4*>(gsr + g * 128 + hh0 + 4);
                float4 na = *reinterpret_cast<const float4*>(gnr + g * 128 + hh0);
                float4 nb = *reinterpret_cast<const float4*>(gnr + g * 128 + hh0 + 4);
                gi[g][0] = sa.x + na.x; gi[g][1] = sa.y + na.y;
                gi[g][2] = sa.z + na.z; gi[g][3] = sa.w + na.w;
                gi[g][4] = sb.x + nb.x; gi[g][5] = sb.y + nb.y;
                gi[g][6] = sb.z + nb.z; gi[g][7] = sb.w + nb.w;
            }
#pragma unroll
            for (int e = 0; e < 8; e++) {
                float r  = sigf(gi[0][e] + acc[0][i][e]);
                float z  = sigf(gi[1][e] + acc[1][i][e]);
                float nn = tanhf(gi[2][e] + r * acc[2][i][e]);
                float hv = (1.0f - z) * nn + z * hprev[i][e];
                hprev[i][e] = hv;
                p0[i] = fmaf(hv, wc0[e], p0[i]);
                p1[i] = fmaf(hv, wc1[e], p1[i]);
                // write back into swizzled hT:  element (k=hh0+e, r=4rg+i)
                hT[(hh0 + e) * 64 + ((rg * 4 + i) ^ (4 * (cg & 7)))] = hv;
            }
        }

        // reduce partial logits across the 16 cg threads of each rg group
#pragma unroll
        for (int o = 8; o; o >>= 1) {
#pragma unroll
            for (int i = 0; i < 4; i++) {
                p0[i] += __shfl_xor_sync(0xFFFFFFFFu, p0[i], o);
                p1[i] += __shfl_xor_sync(0xFFFFFFFFu, p1[i], o);
            }
        }
        if (cg == 0) {
#pragma unroll
            for (int i = 0; i < 4; i++) {
                int row = tb + rg * 4 + i;
                lp[(size_t)row * T_N + t] = make_float2(p0[i], p1[i]);
            }
        }
        __syncthreads();   // hT fully written before next step's GEMM
    }
}

// ============================================================
// hard_w from partial logits + gumbel noise
// ============================================================
__global__ void hard_kernel(const float2* __restrict__ lpf, const float2* __restrict__ lpb,
                            const float* __restrict__ bc, const float* __restrict__ gu,
                            float* __restrict__ hard)
{
    int p = blockIdx.x * 256 + threadIdx.x;
    if (p >= BZ * T_N) return;
    float2 f = lpf[p], b = lpb[p];
    float l0 = f.x + b.x + bc[0];
    float l1 = f.y + b.y + bc[1];
    float u0 = gu[2 * (size_t)p], u1 = gu[2 * (size_t)p + 1];
    float g0 = -logf(-logf(u0 + 1e-10f) + 1e-10f);
    float g1 = -logf(-logf(u1 + 1e-10f) + 1e-10f);
    hard[p] = sigf(((l1 + g1) - (l0 + g0)) / TAUF);
}

// ============================================================
// attention scores + softmax + aggregation.  One warp per (b, i) row.
// ============================================================
__global__ void attn_agg(const float* __restrict__ q, const float* __restrict__ k,
                         const float* __restrict__ hard, const float* __restrict__ hrnn,
                         float* __restrict__ agg)
{
    int warp = threadIdx.x >> 5, lane = threadIdx.x & 31;
    int row = blockIdx.x * 8 + warp;
    int b = row >> 4, i = row & 15;

    float sc = -1e30f, hw = 0.f;
    if (lane < 15) {
        int j = lane + (lane >= i);
        int nrow = (b << 4) | j;
        hw = hard[(size_t)row * 15 + lane];
        const float* qr = q + (size_t)row * NA;
        const float* kr = k + (size_t)nrow * NA;
        float dot = 0.f;
#pragma unroll
        for (int d = 0; d < NA; d++) dot += qr[d] * kr[d];
        sc = dot * hw * 0.17677669529663687f;
    }
    float mx = sc;
#pragma unroll
    for (int o = 16; o; o >>= 1) mx = fmaxf(mx, __shfl_xor_sync(0xFFFFFFFFu, mx, o));
    float ev = (lane < 15) ? expf(sc - mx) : 0.f;
    float se = ev;
#pragma unroll
    for (int o = 16; o; o >>= 1) se += __shfl_xor_sync(0xFFFFFFFFu, se, o);
    float wgt = (lane < 15) ? hw * (ev / se) : 0.f;

#pragma unroll
    for (int c = 0; c < 4; c++) {
        float acc = 0.f;
#pragma unroll
        for (int m = 0; m < 15; m++) {
            float wm = __shfl_sync(0xFFFFFFFFu, wgt, m);
            int jm = m + (m >= i);
            acc += wm * hrnn[(size_t)((b << 4) | jm) * H + c * 32 + lane];
        }
        agg[(size_t)row * H + c * 32 + lane] = acc;
    }
}

// ============================================================
// out = [hrnn | agg] @ W2^T + b2
// ============================================================
__global__ void out_kernel(const float* __restrict__ hrnn, const float* __restrict__ agg,
                           const float* __restrict__ W2, const float* __restrict__ b2,
                           float* __restrict__ out)
{
    __shared__ float w2s[NACT * 256];
    int tid = threadIdx.x;
    for (int x = tid; x < NACT * 256; x += 256) w2s[x] = W2[x];
    __syncthreads();

    int g = blockIdx.x * 256 + tid;
    if (g >= BZ * NACT) return;
    int row = g / NACT, n = g % NACT;
    const float* hr = hrnn + (size_t)row * H;
    const float* ag = agg  + (size_t)row * H;
    float acc = b2[n];
#pragma unroll 4
    for (int kk = 0; kk < 128; kk++) acc += hr[kk] * w2s[n * 256 + kk];
#pragma unroll 4
    for (int kk = 0; kk < 128; kk++) acc += ag[kk] * w2s[n * 256 + 128 + kk];
    out[g] = acc;
}

// ============================================================
extern "C" void kernel_launch(void* const* d_in, const int* in_sizes, int n_in,
                              void* d_out, int out_size)
{
    const float* inputs = (const float*)d_in[0];
    const float* hidden = (const float*)d_in[1];
    const float* gu     = (const float*)d_in[2];
    const float* W1     = (const float*)d_in[3];
    const float* b1     = (const float*)d_in[4];
    const float* Wih_c  = (const float*)d_in[5];
    const float* Whh_c  = (const float*)d_in[6];
    const float* bih_c  = (const float*)d_in[7];
    const float* bhh_c  = (const float*)d_in[8];
    const float* Wih_f  = (const float*)d_in[9];
    const float* Whh_f  = (const float*)d_in[10];
    const float* bih_f  = (const float*)d_in[11];
    const float* bhh_f  = (const float*)d_in[12];
    const float* Wih_b  = (const float*)d_in[13];
    const float* Whh_b  = (const float*)d_in[14];
    const float* bih_b  = (const float*)d_in[15];
    const float* bhh_b  = (const float*)d_in[16];
    const float* Wc     = (const float*)d_in[17];
    const float* bc     = (const float*)d_in[18];
    const float* Wq     = (const float*)d_in[19];
    const float* Wk     = (const float*)d_in[20];
    const float* W2     = (const float*)d_in[21];
    const float* b2     = (const float*)d_in[22];

    float* S = nullptr;
    cudaGetSymbolAddress((void**)&S, g_scratch);

    const size_t U = (size_t)BZ * H;
    const size_t V = (size_t)BZ * G3;
    float* x1   = S;
    float* gi   = x1 + U;
    float* gh   = gi + V;
    float* hrnn = gh + V;
    float* gall = hrnn + U;                       // BZ * 1536
    float* lpfb = gall + (size_t)BZ * 1536;       // 2 * BZ*15 float2
    float2* lpf = (float2*)lpfb;
    float2* lpb = lpf + (size_t)BZ * T_N;
    float* hard = (float*)(lpb + (size_t)BZ * T_N);
    float* qv   = hard + (size_t)BZ * T_N;
    float* kv   = qv + (size_t)BZ * NA;
    float* agg  = kv + (size_t)BZ * NA;

    float* out   = (float*)d_out;
    float* out_h = out + (size_t)BZ * NACT;

    const int RECUR_SMEM = (128 * 384 + 128 * 64) * 4;   // 229376 B
    cudaFuncSetAttribute(recur_fused,
                         cudaFuncAttributeMaxDynamicSharedMemorySize, RECUR_SMEM);

    dim3 blk(256);

    // x1 = relu(inputs @ W1^T + b1)
    sgemm<2><<<dim3(1, BZ/128), blk>>>(inputs, IN_D, W1, IN_D, 0, b1, x1, 128, IN_D);
    // central GRU
    sgemm<1><<<dim3(3, BZ/128), blk>>>(x1,     H, Wih_c, H, 0, bih_c, gi, G3, H);
    sgemm<1><<<dim3(3, BZ/128), blk>>>(hidden, H, Whh_c, H, 0, bhh_c, gh, G3, H);
    gru_central<<<BZ * H / 256, blk>>>(gi, gh, hidden, hrnn, out_h);

    // packed input-gate precompute [gsf|gnf|gsb|gnb]
    sgemm_ih<<<dim3(12, BZ/128), blk>>>(hrnn, Wih_f, bih_f, Wih_b, bih_b, gall);

    // q, k projections (independent of recurrence)
    sgemm<0><<<dim3(1, BZ/128), blk>>>(hrnn, H, Wq, H, 0, nullptr, qv, NA, H);
    sgemm<0><<<dim3(1, BZ/128), blk>>>(hrnn, H, Wk, H, 0, nullptr, kv, NA, H);

    // fused persistent bi-GRU recurrence (also emits partial logits)
    recur_fused<<<512, blk, RECUR_SMEM>>>(gall, Whh_f, bhh_f, Whh_b, bhh_b,
                                          Wc, lpf, lpb);

    // gumbel hard weights from partial logits
    hard_kernel<<<(BZ * T_N + 255) / 256, blk>>>(lpf, lpb, bc, gu, hard);

    // attention + aggregation
    attn_agg<<<BZ / 8, blk>>>(qv, kv, hard, hrnn, agg);

    // output head
    out_kernel<<<(BZ * NACT + 255) / 256, blk>>>(hrnn, agg, W2, b2, out);
}

// round 14
// speedup vs baseline: 2.4249x; 1.8434x over previous
#include <cuda_runtime.h>
#include <cuda_bf16.h>
#include <math.h>
#include <stdint.h>

#define A_N   16
#define H     128
#define IN_D  128
#define NA    32
#define NACT  14
#define TAUF  0.5f
#define BZ    16384
#define T_N   15
#define G3    384   // 3*H

static __device__ float g_scratch[125026304];

__device__ __forceinline__ float sigf(float x){ return 1.0f/(1.0f+expf(-x)); }

// ============================================================
// warp-level bf16 MMA m16n8k16 (baseline PTX, works on sm_103)
// ============================================================
__device__ __forceinline__ void hmma(float* d, const uint32_t* a, uint32_t b0, uint32_t b1){
    asm volatile("mma.sync.aligned.m16n8k16.row.col.f32.bf16.bf16.f32 "
        "{%0,%1,%2,%3}, {%4,%5,%6,%7}, {%8,%9}, {%0,%1,%2,%3};"
        : "+f"(d[0]), "+f"(d[1]), "+f"(d[2]), "+f"(d[3])
        : "r"(a[0]), "r"(a[1]), "r"(a[2]), "r"(a[3]), "r"(b0), "r"(b1));
}
__device__ __forceinline__ uint32_t packbf(float x, float y){
    __nv_bfloat162 t = __floats2bfloat162_rn(x, y);   // low = x, high = y
    return *reinterpret_cast<uint32_t*>(&t);
}

// ============================================================
// Generic SGEMM (SIMT): C = A @ W^T (+bias)(+relu). 128x128 tile, BK=8.
// ============================================================
template<int EPI>
__global__ void sgemm(const float* __restrict__ Amat, int lda,
                      const float* __restrict__ W, int ldw, int wofs,
                      const float* __restrict__ bias,
                      float* __restrict__ C, int N, int K)
{
    __shared__ float As[8][128];
    __shared__ float Bs[8][128];
    const int tid = threadIdx.x;
    const int rowBase = blockIdx.y * 128;
    const int colBase = blockIdx.x * 128;
    const int lr = tid >> 1;
    const int lc = (tid & 1) * 4;

    float acc[8][8];
#pragma unroll
    for (int i = 0; i < 8; i++)
#pragma unroll
        for (int j = 0; j < 8; j++) acc[i][j] = 0.0f;

    const int ty = tid >> 4;
    const int tx = tid & 15;

    for (int k0 = 0; k0 < K; k0 += 8) {
        float4 av = *reinterpret_cast<const float4*>(
            Amat + (size_t)(rowBase + lr) * lda + k0 + lc);
        int n = colBase + lr;
        float4 bv = make_float4(0.f, 0.f, 0.f, 0.f);
        if (n < N)
            bv = *reinterpret_cast<const float4*>(
                W + (size_t)n * ldw + wofs + k0 + lc);

        As[lc + 0][lr] = av.x; As[lc + 1][lr] = av.y;
        As[lc + 2][lr] = av.z; As[lc + 3][lr] = av.w;
        Bs[lc + 0][lr] = bv.x; Bs[lc + 1][lr] = bv.y;
        Bs[lc + 2][lr] = bv.z; Bs[lc + 3][lr] = bv.w;
        __syncthreads();

#pragma unroll
        for (int kk = 0; kk < 8; kk++) {
            float a[8], b[8];
            *reinterpret_cast<float4*>(a)     = *reinterpret_cast<const float4*>(&As[kk][ty*8]);
            *reinterpret_cast<float4*>(a + 4) = *reinterpret_cast<const float4*>(&As[kk][ty*8+4]);
            *reinterpret_cast<float4*>(b)     = *reinterpret_cast<const float4*>(&Bs[kk][tx*8]);
            *reinterpret_cast<float4*>(b + 4) = *reinterpret_cast<const float4*>(&Bs[kk][tx*8+4]);
#pragma unroll
            for (int i = 0; i < 8; i++)
#pragma unroll
                for (int j = 0; j < 8; j++)
                    acc[i][j] = fmaf(a[i], b[j], acc[i][j]);
        }
        __syncthreads();
    }

#pragma unroll
    for (int i = 0; i < 8; i++) {
        int m = rowBase + ty * 8 + i;
#pragma unroll
        for (int j = 0; j < 8; j++) {
            int n = colBase + tx * 8 + j;
            if (n < N) {
                float v = acc[i][j];
                if (EPI >= 1) v += bias[n];
                if (EPI == 2) v = fmaxf(v, 0.0f);
                C[(size_t)m * N + n] = v;
            }
        }
    }
}

// ============================================================
// Packed input-gate GEMM: gall[BZ][1536] = [gsf|gnf|gsb|gnb]
// ============================================================
__global__ void sgemm_ih(const float* __restrict__ Amat,
                         const float* __restrict__ Wih_f, const float* __restrict__ bih_f,
                         const float* __restrict__ Wih_b, const float* __restrict__ bih_b,
                         float* __restrict__ C)
{
    __shared__ float As[8][128];
    __shared__ float Bs[8][128];
    const int tid = threadIdx.x;
    const int rowBase = blockIdx.y * 128;
    const int T = blockIdx.x;
    const int colBase = T * 128;
    const int midx = T / 3;
    const float* W = (midx < 2) ? Wih_f : Wih_b;
    const int wofs = (midx & 1) ? 128 : 0;
    const float* bias = (midx == 0) ? bih_f : (midx == 2) ? bih_b : nullptr;
    const int nlBase = colBase - midx * 384;

    const int lr = tid >> 1;
    const int lc = (tid & 1) * 4;

    float acc[8][8];
#pragma unroll
    for (int i = 0; i < 8; i++)
#pragma unroll
        for (int j = 0; j < 8; j++) acc[i][j] = 0.0f;

    const int ty = tid >> 4;
    const int tx = tid & 15;

    for (int k0 = 0; k0 < 128; k0 += 8) {
        float4 av = *reinterpret_cast<const float4*>(
            Amat + (size_t)(rowBase + lr) * 128 + k0 + lc);
        float4 bv = *reinterpret_cast<const float4*>(
            W + (size_t)(nlBase + lr) * 256 + wofs + k0 + lc);

        As[lc + 0][lr] = av.x; As[lc + 1][lr] = av.y;
        As[lc + 2][lr] = av.z; As[lc + 3][lr] = av.w;
        Bs[lc + 0][lr] = bv.x; Bs[lc + 1][lr] = bv.y;
        Bs[lc + 2][lr] = bv.z; Bs[lc + 3][lr] = bv.w;
        __syncthreads();

#pragma unroll
        for (int kk = 0; kk < 8; kk++) {
            float a[8], b[8];
            *reinterpret_cast<float4*>(a)     = *reinterpret_cast<const float4*>(&As[kk][ty*8]);
            *reinterpret_cast<float4*>(a + 4) = *reinterpret_cast<const float4*>(&As[kk][ty*8+4]);
            *reinterpret_cast<float4*>(b)     = *reinterpret_cast<const float4*>(&Bs[kk][tx*8]);
            *reinterpret_cast<float4*>(b + 4) = *reinterpret_cast<const float4*>(&Bs[kk][tx*8+4]);
#pragma unroll
            for (int i = 0; i < 8; i++)
#pragma unroll
                for (int j = 0; j < 8; j++)
                    acc[i][j] = fmaf(a[i], b[j], acc[i][j]);
        }
        __syncthreads();
    }

#pragma unroll
    for (int i = 0; i < 8; i++) {
        int m = rowBase + ty * 8 + i;
#pragma unroll
        for (int j = 0; j < 8; j++) {
            int n = colBase + tx * 8 + j;
            float v = acc[i][j];
            if (bias) v += bias[nlBase + tx * 8 + j];
            C[(size_t)m * 1536 + n] = v;
        }
    }
}

// ============================================================
// Central GRU combine
// ============================================================
__global__ void gru_central(const float* __restrict__ gi, const float* __restrict__ gh,
                            const float* __restrict__ hprev,
                            float* __restrict__ hrnn, float* __restrict__ out_h)
{
    int e = blockIdx.x * 256 + threadIdx.x;
    int row = e >> 7, hh = e & 127;
    size_t base = (size_t)row * G3;
    float r = sigf(gi[base + hh]        + gh[base + hh]);
    float z = sigf(gi[base + 128 + hh]  + gh[base + 128 + hh]);
    float n = tanhf(gi[base + 256 + hh] + r * gh[base + 256 + hh]);
    float hv = (1.0f - z) * n + z * hprev[e];
    hrnn[e]  = hv;
    out_h[e] = hv;
}

// ============================================================
// HMMA persistent bi-GRU recurrence.
// CTA = 128 rows × one direction, all 15 steps.  8 warps; warp w owns
// rows [w*16, w*16+16): D-fragment rows r0 = w*16+lane/4, r1 = r0+8.
// smem: Whh bf16 hi/lo, word-XOR swizzle (w ^ 4*(n&7)) -> conflict-free
//       B-fragment LDS.  192 KB.
// h stays in registers: hprev[16][4] fp32 in D-fragment layout doubles as
// the A-fragment source (m16n8 D layout == m16k16 A layout halves).
// 3-term bf16 split: D = Ah*Bh + Al*Bh + Ah*Bl, fp32 accumulate.
// Per-step Wc logit partials reduced over the 4 lanes of each row group.
// ============================================================
#define BLW 24576            // 384*64 words per buffer
#define RECUR_DYN (2 * BLW * 4)

__global__ __launch_bounds__(256, 1)
void recur_mma(const float* __restrict__ gall,
               const float* __restrict__ Whh_f, const float* __restrict__ bhh_f,
               const float* __restrict__ Whh_b, const float* __restrict__ bhh_b,
               const float* __restrict__ Wc,
               float2* __restrict__ lpf, float2* __restrict__ lpb)
{
    extern __shared__ uint32_t smw[];        // [hi: BLW][lo: BLW]
    __shared__ float sbhh[384];
    __shared__ float swc[256];

    const int tid  = threadIdx.x;
    const int w    = tid >> 5, lane = tid & 31;
    const int qr   = lane >> 2;              // 0..7  (fragment row group)
    const int qc   = lane & 3;               // 0..3  (fragment col group)
    const int dir  = blockIdx.y;
    const int tb   = blockIdx.x * 128;
    const int r0   = tb + w * 16 + qr;
    const int r1   = r0 + 8;
    const int bb   = r0 >> 4;                // same group for r0, r1
    const int i0   = qr, i1 = qr + 8;        // agent indices
    const int gofs = dir ? 768 : 0;

    const float* Whh = dir ? Whh_b : Whh_f;
    const float* bhh = dir ? bhh_b : bhh_f;
    float2* lp = dir ? lpb : lpf;

    // ---- Whh -> bf16 hi/lo, XOR-swizzled words ----
    for (int idx = tid; idx < 384 * 64; idx += 256) {
        int n = idx >> 6, ww = idx & 63;
        float2 v = *reinterpret_cast<const float2*>(Whh + (size_t)n * 128 + 2 * ww);
        __nv_bfloat16 h0 = __float2bfloat16(v.x);
        __nv_bfloat16 h1 = __float2bfloat16(v.y);
        __nv_bfloat16 l0 = __float2bfloat16(v.x - __bfloat162float(h0));
        __nv_bfloat16 l1 = __float2bfloat16(v.y - __bfloat162float(h1));
        int ws = ww ^ (4 * (n & 7));
        smw[n * 64 + ws] = (uint32_t)__bfloat16_as_ushort(h0)
                         | ((uint32_t)__bfloat16_as_ushort(h1) << 16);
        smw[BLW + n * 64 + ws] = (uint32_t)__bfloat16_as_ushort(l0)
                               | ((uint32_t)__bfloat16_as_ushort(l1) << 16);
    }
    for (int q = tid; q < 384; q += 256) sbhh[q] = bhh[q];
    if (tid < 128) {
        swc[tid]       = Wc[dir * 128 + tid];
        swc[128 + tid] = Wc[256 + dir * 128 + tid];
    }
    __syncthreads();

    // hprev[T][j]: tile T covers cols T*8 + 2*qc + {0,1}; j = {r0c0,r0c1,r1c0,r1c1}
    float hprev[16][4];
#pragma unroll
    for (int T = 0; T < 16; T++)
#pragma unroll
        for (int j = 0; j < 4; j++) hprev[T][j] = 0.0f;

    const float* gs0 = gall + (size_t)r0 * 1536 + gofs;
    const float* gs1 = gall + (size_t)r1 * 1536 + gofs;

    for (int s = 0; s < T_N; s++) {
        const int t = dir ? (T_N - 1 - s) : s;
        const int j0 = t + (t >= i0);
        const int j1 = t + (t >= i1);
        const float* gn0 = gall + (size_t)((bb << 4) | j0) * 1536 + gofs + 384;
        const float* gn1 = gall + (size_t)((bb << 4) | j1) * 1536 + gofs + 384;

        // ---- build A fragments (bf16 hi/lo) from hprev ----
        uint32_t Ah[32], Al[32];
#pragma unroll
        for (int kc = 0; kc < 8; kc++) {
#pragma unroll
            for (int half = 0; half < 2; half++) {       // tile 2kc+half
                const float* hv = hprev[2 * kc + half];
                float e0 = hv[0], e1 = hv[1], e2 = hv[2], e3 = hv[3];
                uint32_t h01 = packbf(e0, e1);
                uint32_t h23 = packbf(e2, e3);
                __nv_bfloat162 bh01 = *reinterpret_cast<__nv_bfloat162*>(&h01);
                __nv_bfloat162 bh23 = *reinterpret_cast<__nv_bfloat162*>(&h23);
                Ah[kc * 4 + 2 * half + 0] = h01;   // rows r0, k pair
                Ah[kc * 4 + 2 * half + 1] = h23;   // rows r1, k pair
                Al[kc * 4 + 2 * half + 0] =
                    packbf(e0 - __bfloat162float(bh01.x), e1 - __bfloat162float(bh01.y));
                Al[kc * 4 + 2 * half + 1] =
                    packbf(e2 - __bfloat162float(bh23.x), e3 - __bfloat162float(bh23.y));
            }
        }
        // reorder: A-frag for kc is {Ah[kc*4+0](r0,k0..), Ah[kc*4+1](r1,k0..),
        //                            Ah[kc*4+2](r0,k8..), Ah[kc*4+3](r1,k8..)}
        // which matches {a0,a1,a2,a3} of m16n8k16.

        float p0r0 = 0.f, p1r0 = 0.f, p0r1 = 0.f, p1r1 = 0.f;

#pragma unroll
        for (int c = 0; c < 4; c++) {                    // 32-col chunks
            float acc[3][4][4];
#pragma unroll
            for (int g3 = 0; g3 < 3; g3++)
#pragma unroll
                for (int tt = 0; tt < 4; tt++)
#pragma unroll
                    for (int j = 0; j < 4; j++) acc[g3][tt][j] = 0.0f;

#pragma unroll
            for (int kc = 0; kc < 8; kc++) {
                const uint32_t* ah = Ah + kc * 4;
                const uint32_t* al = Al + kc * 4;
#pragma unroll
                for (int g3 = 0; g3 < 3; g3++) {
#pragma unroll
                    for (int tt = 0; tt < 4; tt++) {
                        int n   = g3 * 128 + c * 32 + tt * 8 + qr;
                        int w0  = kc * 8 + qc;
                        int sx  = 4 * (n & 7);
                        uint32_t bh0 = smw[n * 64 + (w0 ^ sx)];
                        uint32_t bh1 = smw[n * 64 + ((w0 + 4) ^ sx)];
                        uint32_t bl0 = smw[BLW + n * 64 + (w0 ^ sx)];
                        uint32_t bl1 = smw[BLW + n * 64 + ((w0 + 4) ^ sx)];
                        hmma(acc[g3][tt], ah, bh0, bh1);
                        hmma(acc[g3][tt], al, bh0, bh1);
                        hmma(acc[g3][tt], ah, bl0, bl1);
                    }
                }
            }

            // ---- gate combine for tiles T = 4c..4c+3 ----
#pragma unroll
            for (int tt = 0; tt < 4; tt++) {
                int T  = c * 4 + tt;
                int co = T * 8 + 2 * qc;
                float2 sr0 = *reinterpret_cast<const float2*>(gs0 + co);
                float2 nr0 = *reinterpret_cast<const float2*>(gn0 + co);
                float2 sr1 = *reinterpret_cast<const float2*>(gs1 + co);
                float2 nr1 = *reinterpret_cast<const float2*>(gn1 + co);
                float2 sz0 = *reinterpret_cast<const float2*>(gs0 + 128 + co);
                float2 nz0 = *reinterpret_cast<const float2*>(gn0 + 128 + co);
                float2 sz1 = *reinterpret_cast<const float2*>(gs1 + 128 + co);
                float2 nz1 = *reinterpret_cast<const float2*>(gn1 + 128 + co);
                float2 sn0 = *reinterpret_cast<const float2*>(gs0 + 256 + co);
                float2 nn0 = *reinterpret_cast<const float2*>(gn0 + 256 + co);
                float2 sn1 = *reinterpret_cast<const float2*>(gs1 + 256 + co);
                float2 nn1 = *reinterpret_cast<const float2*>(gn1 + 256 + co);

                float gir[4] = { sr0.x + nr0.x, sr0.y + nr0.y, sr1.x + nr1.x, sr1.y + nr1.y };
                float giz[4] = { sz0.x + nz0.x, sz0.y + nz0.y, sz1.x + nz1.x, sz1.y + nz1.y };
                float gin[4] = { sn0.x + nn0.x, sn0.y + nn0.y, sn1.x + nn1.x, sn1.y + nn1.y };

                float hv[4];
#pragma unroll
                for (int j = 0; j < 4; j++) {
                    int col = co + (j & 1);
                    float rr = sigf(gir[j] + acc[0][tt][j] + sbhh[col]);
                    float zz = sigf(giz[j] + acc[1][tt][j] + sbhh[128 + col]);
                    float nn = tanhf(gin[j] + rr * (acc[2][tt][j] + sbhh[256 + col]));
                    float h  = (1.0f - zz) * nn + zz * hprev[T][j];
                    hprev[T][j] = h;
                    hv[j] = h;
                }
                p0r0 = fmaf(hv[0], swc[co], fmaf(hv[1], swc[co + 1], p0r0));
                p1r0 = fmaf(hv[0], swc[128 + co], fmaf(hv[1], swc[128 + co + 1], p1r0));
                p0r1 = fmaf(hv[2], swc[co], fmaf(hv[3], swc[co + 1], p0r1));
                p1r1 = fmaf(hv[2], swc[128 + co], fmaf(hv[3], swc[128 + co + 1], p1r1));
            }
        }

        // reduce logit partials over the 4 qc lanes of each row group
#pragma unroll
        for (int o = 1; o <= 2; o <<= 1) {
            p0r0 += __shfl_xor_sync(0xFFFFFFFFu, p0r0, o);
            p1r0 += __shfl_xor_sync(0xFFFFFFFFu, p1r0, o);
            p0r1 += __shfl_xor_sync(0xFFFFFFFFu, p0r1, o);
            p1r1 += __shfl_xor_sync(0xFFFFFFFFu, p1r1, o);
        }
        if (qc == 0) {
            lp[(size_t)r0 * T_N + t] = make_float2(p0r0, p1r0);
            lp[(size_t)r1 * T_N + t] = make_float2(p0r1, p1r1);
        }
    }
}

// ============================================================
// hard_w from partial logits + gumbel noise
// ============================================================
__global__ void hard_kernel(const float2* __restrict__ lpf, const float2* __restrict__ lpb,
                            const float* __restrict__ bc, const float* __restrict__ gu,
                            float* __restrict__ hard)
{
    int p = blockIdx.x * 256 + threadIdx.x;
    if (p >= BZ * T_N) return;
    float2 f = lpf[p], b = lpb[p];
    float l0 = f.x + b.x + bc[0];
    float l1 = f.y + b.y + bc[1];
    float u0 = gu[2 * (size_t)p], u1 = gu[2 * (size_t)p + 1];
    float g0 = -logf(-logf(u0 + 1e-10f) + 1e-10f);
    float g1 = -logf(-logf(u1 + 1e-10f) + 1e-10f);
    hard[p] = sigf(((l1 + g1) - (l0 + g0)) / TAUF);
}

// ============================================================
// attention scores + softmax + aggregation.  One warp per (b, i) row.
// ============================================================
__global__ void attn_agg(const float* __restrict__ q, const float* __restrict__ k,
                         const float* __restrict__ hard, const float* __restrict__ hrnn,
                         float* __restrict__ agg)
{
    int warp = threadIdx.x >> 5, lane = threadIdx.x & 31;
    int row = blockIdx.x * 8 + warp;
    int b = row >> 4, i = row & 15;

    float sc = -1e30f, hw = 0.f;
    if (lane < 15) {
        int j = lane + (lane >= i);
        int nrow = (b << 4) | j;
        hw = hard[(size_t)row * 15 + lane];
        const float* qr = q + (size_t)row * NA;
        const float* kr = k + (size_t)nrow * NA;
        float dot = 0.f;
#pragma unroll
        for (int d = 0; d < NA; d++) dot += qr[d] * kr[d];
        sc = dot * hw * 0.17677669529663687f;
    }
    float mx = sc;
#pragma unroll
    for (int o = 16; o; o >>= 1) mx = fmaxf(mx, __shfl_xor_sync(0xFFFFFFFFu, mx, o));
    float ev = (lane < 15) ? expf(sc - mx) : 0.f;
    float se = ev;
#pragma unroll
    for (int o = 16; o; o >>= 1) se += __shfl_xor_sync(0xFFFFFFFFu, se, o);
    float wgt = (lane < 15) ? hw * (ev / se) : 0.f;

#pragma unroll
    for (int c = 0; c < 4; c++) {
        float acc = 0.f;
#pragma unroll
        for (int m = 0; m < 15; m++) {
            float wm = __shfl_sync(0xFFFFFFFFu, wgt, m);
            int jm = m + (m >= i);
            acc += wm * hrnn[(size_t)((b << 4) | jm) * H + c * 32 + lane];
        }
        agg[(size_t)row * H + c * 32 + lane] = acc;
    }
}

// ============================================================
// out = [hrnn | agg] @ W2^T + b2
// ============================================================
__global__ void out_kernel(const float* __restrict__ hrnn, const float* __restrict__ agg,
                           const float* __restrict__ W2, const float* __restrict__ b2,
                           float* __restrict__ out)
{
    __shared__ float w2s[NACT * 256];
    int tid = threadIdx.x;
    for (int x = tid; x < NACT * 256; x += 256) w2s[x] = W2[x];
    __syncthreads();

    int g = blockIdx.x * 256 + tid;
    if (g >= BZ * NACT) return;
    int row = g / NACT, n = g % NACT;
    const float* hr = hrnn + (size_t)row * H;
    const float* ag = agg  + (size_t)row * H;
    float acc = b2[n];
#pragma unroll 4
    for (int kk = 0; kk < 128; kk++) acc += hr[kk] * w2s[n * 256 + kk];
#pragma unroll 4
    for (int kk = 0; kk < 128; kk++) acc += ag[kk] * w2s[n * 256 + 128 + kk];
    out[g] = acc;
}

// ============================================================
extern "C" void kernel_launch(void* const* d_in, const int* in_sizes, int n_in,
                              void* d_out, int out_size)
{
    const float* inputs = (const float*)d_in[0];
    const float* hidden = (const float*)d_in[1];
    const float* gu     = (const float*)d_in[2];
    const float* W1     = (const float*)d_in[3];
    const float* b1     = (const float*)d_in[4];
    const float* Wih_c  = (const float*)d_in[5];
    const float* Whh_c  = (const float*)d_in[6];
    const float* bih_c  = (const float*)d_in[7];
    const float* bhh_c  = (const float*)d_in[8];
    const float* Wih_f  = (const float*)d_in[9];
    const float* Whh_f  = (const float*)d_in[10];
    const float* bih_f  = (const float*)d_in[11];
    const float* bhh_f  = (const float*)d_in[12];
    const float* Wih_b  = (const float*)d_in[13];
    const float* Whh_b  = (const float*)d_in[14];
    const float* bih_b  = (const float*)d_in[15];
    const float* bhh_b  = (const float*)d_in[16];
    const float* Wc     = (const float*)d_in[17];
    const float* bc     = (const float*)d_in[18];
    const float* Wq     = (const float*)d_in[19];
    const float* Wk     = (const float*)d_in[20];
    const float* W2     = (const float*)d_in[21];
    const float* b2     = (const float*)d_in[22];

    float* S = nullptr;
    cudaGetSymbolAddress((void**)&S, g_scratch);

    const size_t U = (size_t)BZ * H;
    const size_t V = (size_t)BZ * G3;
    float* x1   = S;
    float* gi   = x1 + U;
    float* gh   = gi + V;
    float* hrnn = gh + V;
    float* gall = hrnn + U;                       // BZ * 1536
    float* lpfb = gall + (size_t)BZ * 1536;
    float2* lpf = (float2*)lpfb;
    float2* lpb = lpf + (size_t)BZ * T_N;
    float* hard = (float*)(lpb + (size_t)BZ * T_N);
    float* qv   = hard + (size_t)BZ * T_N;
    float* kv   = qv + (size_t)BZ * NA;
    float* agg  = kv + (size_t)BZ * NA;

    float* out   = (float*)d_out;
    float* out_h = out + (size_t)BZ * NACT;

    cudaFuncSetAttribute(recur_mma,
                         cudaFuncAttributeMaxDynamicSharedMemorySize, RECUR_DYN);

    dim3 blk(256);

    // x1 = relu(inputs @ W1^T + b1)
    sgemm<2><<<dim3(1, BZ/128), blk>>>(inputs, IN_D, W1, IN_D, 0, b1, x1, 128, IN_D);
    // central GRU
    sgemm<1><<<dim3(3, BZ/128), blk>>>(x1,     H, Wih_c, H, 0, bih_c, gi, G3, H);
    sgemm<1><<<dim3(3, BZ/128), blk>>>(hidden, H, Whh_c, H, 0, bhh_c, gh, G3, H);
    gru_central<<<BZ * H / 256, blk>>>(gi, gh, hidden, hrnn, out_h);

    // packed input-gate precompute [gsf|gnf|gsb|gnb]
    sgemm_ih<<<dim3(12, BZ/128), blk>>>(hrnn, Wih_f, bih_f, Wih_b, bih_b, gall);

    // q, k projections (independent of recurrence)
    sgemm<0><<<dim3(1, BZ/128), blk>>>(hrnn, H, Wq, H, 0, nullptr, qv, NA, H);
    sgemm<0><<<dim3(1, BZ/128), blk>>>(hrnn, H, Wk, H, 0, nullptr, kv, NA, H);

    // HMMA persistent bi-GRU recurrence
    recur_mma<<<dim3(BZ/128, 2), blk, RECUR_DYN>>>(gall, Whh_f, bhh_f, Whh_b, bhh_b,
                                                   Wc, lpf, lpb);

    // gumbel hard weights
    hard_kernel<<<(BZ * T_N + 255) / 256, blk>>>(lpf, lpb, bc, gu, hard);

    // attention + aggregation
    attn_agg<<<BZ / 8, blk>>>(qv, kv, hard, hrnn, agg);

    // output head
    out_kernel<<<(BZ * NACT + 255) / 256, blk>>>(hrnn, agg, W2, b2, out);
}

// round 15
// speedup vs baseline: 3.0909x; 1.2746x over previous
#include <cuda_runtime.h>
#include <cuda_bf16.h>
#include <math.h>
#include <stdint.h>

#define A_N   16
#define H     128
#define IN_D  128
#define NA    32
#define NACT  14
#define TAUF  0.5f
#define BZ    16384
#define T_N   15
#define G3    384   // 3*H

static __device__ float g_scratch[125026304];

__device__ __forceinline__ float sigf(float x){ return 1.0f/(1.0f+expf(-x)); }

// ============================================================
// warp-level bf16 MMA m16n8k16 (baseline PTX, works on sm_103)
// ============================================================
__device__ __forceinline__ void hmma(float* d, const uint32_t* a, uint32_t b0, uint32_t b1){
    asm volatile("mma.sync.aligned.m16n8k16.row.col.f32.bf16.bf16.f32 "
        "{%0,%1,%2,%3}, {%4,%5,%6,%7}, {%8,%9}, {%0,%1,%2,%3};"
        : "+f"(d[0]), "+f"(d[1]), "+f"(d[2]), "+f"(d[3])
        : "r"(a[0]), "r"(a[1]), "r"(a[2]), "r"(a[3]), "r"(b0), "r"(b1));
}
__device__ __forceinline__ uint32_t packbf(float x, float y){
    __nv_bfloat162 t = __floats2bfloat162_rn(x, y);   // low = x, high = y
    return *reinterpret_cast<uint32_t*>(&t);
}
__device__ __forceinline__ void packsplit(float x, float y, uint32_t& hi, uint32_t& lo){
    uint32_t h = packbf(x, y);
    __nv_bfloat162 bh = *reinterpret_cast<__nv_bfloat162*>(&h);
    hi = h;
    lo = packbf(x - __bfloat162float(bh.x), y - __bfloat162float(bh.y));
}

#define HSMEM 65536   // 2 * 8192 words * 4B (hi + lo W tile)

// ============================================================
// HMMA GEMM: C[m,n] = sum_k A[m*lda+k] * W[n*ldw+wofs+k] (+bias)(+relu)
// K=128 fixed.  CTA = 128 rows x 128-col block; warp = 16 rows.
// 3-term bf16 split, fp32 accumulate.  EPI: 0 none, 1 bias, 2 bias+relu.
// ============================================================
template<int EPI>
__global__ __launch_bounds__(256)
void hgemm(const float* __restrict__ A, int lda,
           const float* __restrict__ W, int ldw, int wofs,
           const float* __restrict__ bias,
           float* __restrict__ C, int ldc, int N)
{
    extern __shared__ uint32_t smw[];     // [hi: 8192][lo: 8192]
    const int tid = threadIdx.x;
    const int w = tid >> 5, lane = tid & 31;
    const int qr = lane >> 2, qc = lane & 3;
    const int colBase = blockIdx.x * 128;
    const int r0 = blockIdx.y * 128 + w * 16 + qr;
    const int r1 = r0 + 8;

    // ---- W tile -> bf16 hi/lo swizzled smem ----
    for (int idx = tid; idx < 128 * 64; idx += 256) {
        int n = idx >> 6, ww = idx & 63;
        int gn = colBase + n;
        float2 v = make_float2(0.f, 0.f);
        if (gn < N)
            v = *reinterpret_cast<const float2*>(W + (size_t)gn * ldw + wofs + 2 * ww);
        uint32_t hi, lo; packsplit(v.x, v.y, hi, lo);
        int ws = ww ^ (4 * (n & 7));
        smw[n * 64 + ws]        = hi;
        smw[8192 + n * 64 + ws] = lo;
    }

    // ---- A rows -> registers -> bf16 hi/lo fragments ----
    float av[16][4];
#pragma unroll
    for (int T = 0; T < 16; T++) {
        float2 p0 = *reinterpret_cast<const float2*>(A + (size_t)r0 * lda + T * 8 + 2 * qc);
        float2 p1 = *reinterpret_cast<const float2*>(A + (size_t)r1 * lda + T * 8 + 2 * qc);
        av[T][0] = p0.x; av[T][1] = p0.y; av[T][2] = p1.x; av[T][3] = p1.y;
    }
    uint32_t Ah[32], Al[32];
#pragma unroll
    for (int kc = 0; kc < 8; kc++) {
#pragma unroll
        for (int half = 0; half < 2; half++) {
            const float* hv = av[2 * kc + half];
            packsplit(hv[0], hv[1], Ah[kc * 4 + 2 * half + 0], Al[kc * 4 + 2 * half + 0]);
            packsplit(hv[2], hv[3], Ah[kc * 4 + 2 * half + 1], Al[kc * 4 + 2 * half + 1]);
        }
    }
    __syncthreads();

    float acc[16][4];
#pragma unroll
    for (int tt = 0; tt < 16; tt++)
#pragma unroll
        for (int j = 0; j < 4; j++) acc[tt][j] = 0.0f;

#pragma unroll
    for (int kc = 0; kc < 8; kc++) {
        const uint32_t* ah = Ah + kc * 4;
        const uint32_t* al = Al + kc * 4;
#pragma unroll
        for (int tt = 0; tt < 16; tt++) {
            int n  = tt * 8 + qr;
            int w0 = kc * 8 + qc;
            int sx = 4 * (n & 7);
            uint32_t bh0 = smw[n * 64 + (w0 ^ sx)];
            uint32_t bh1 = smw[n * 64 + ((w0 + 4) ^ sx)];
            uint32_t bl0 = smw[8192 + n * 64 + (w0 ^ sx)];
            uint32_t bl1 = smw[8192 + n * 64 + ((w0 + 4) ^ sx)];
            hmma(acc[tt], ah, bh0, bh1);
            hmma(acc[tt], al, bh0, bh1);
            hmma(acc[tt], ah, bl0, bl1);
        }
    }

#pragma unroll
    for (int tt = 0; tt < 16; tt++) {
        int n0 = colBase + tt * 8 + 2 * qc;
        if (n0 < N) {
            float b0 = 0.f, b1 = 0.f;
            if (EPI >= 1) { b0 = bias[n0]; b1 = bias[n0 + 1]; }
            float v0 = acc[tt][0] + b0, v1 = acc[tt][1] + b1;
            float v2 = acc[tt][2] + b0, v3 = acc[tt][3] + b1;
            if (EPI == 2) {
                v0 = fmaxf(v0, 0.f); v1 = fmaxf(v1, 0.f);
                v2 = fmaxf(v2, 0.f); v3 = fmaxf(v3, 0.f);
            }
            *reinterpret_cast<float2*>(C + (size_t)r0 * ldc + n0) = make_float2(v0, v1);
            *reinterpret_cast<float2*>(C + (size_t)r1 * ldc + n0) = make_float2(v2, v3);
        }
    }
}

// ============================================================
// HMMA packed input-gate GEMM: gall[BZ][1536] = [gsf|gnf|gsb|gnb]
// col-block T (0..11) selects the weight slice (R6 bias-fix layout).
// ============================================================
__global__ __launch_bounds__(256)
void hgemm_ih(const float* __restrict__ A,
              const float* __restrict__ Wih_f, const float* __restrict__ bih_f,
              const float* __restrict__ Wih_b, const float* __restrict__ bih_b,
              float* __restrict__ C)
{
    extern __shared__ uint32_t smw[];
    const int tid = threadIdx.x;
    const int w = tid >> 5, lane = tid & 31;
    const int qr = lane >> 2, qc = lane & 3;
    const int T = blockIdx.x;                // 0..11
    const int colBase = T * 128;
    const int midx = T / 3;
    const float* W = (midx < 2) ? Wih_f : Wih_b;
    const int wofs = (midx & 1) ? 128 : 0;
    const float* bias = (midx == 0) ? bih_f : (midx == 2) ? bih_b : nullptr;
    const int nlBase = colBase - midx * 384; // 0 / 128 / 256
    const int r0 = blockIdx.y * 128 + w * 16 + qr;
    const int r1 = r0 + 8;

    for (int idx = tid; idx < 128 * 64; idx += 256) {
        int n = idx >> 6, ww = idx & 63;
        float2 v = *reinterpret_cast<const float2*>(
            W + (size_t)(nlBase + n) * 256 + wofs + 2 * ww);
        uint32_t hi, lo; packsplit(v.x, v.y, hi, lo);
        int ws = ww ^ (4 * (n & 7));
        smw[n * 64 + ws]        = hi;
        smw[8192 + n * 64 + ws] = lo;
    }

    float av[16][4];
#pragma unroll
    for (int t2 = 0; t2 < 16; t2++) {
        float2 p0 = *reinterpret_cast<const float2*>(A + (size_t)r0 * 128 + t2 * 8 + 2 * qc);
        float2 p1 = *reinterpret_cast<const float2*>(A + (size_t)r1 * 128 + t2 * 8 + 2 * qc);
        av[t2][0] = p0.x; av[t2][1] = p0.y; av[t2][2] = p1.x; av[t2][3] = p1.y;
    }
    uint32_t Ah[32], Al[32];
#pragma unroll
    for (int kc = 0; kc < 8; kc++) {
#pragma unroll
        for (int half = 0; half < 2; half++) {
            const float* hv = av[2 * kc + half];
            packsplit(hv[0], hv[1], Ah[kc * 4 + 2 * half + 0], Al[kc * 4 + 2 * half + 0]);
            packsplit(hv[2], hv[3], Ah[kc * 4 + 2 * half + 1], Al[kc * 4 + 2 * half + 1]);
        }
    }
    __syncthreads();

    float acc[16][4];
#pragma unroll
    for (int tt = 0; tt < 16; tt++)
#pragma unroll
        for (int j = 0; j < 4; j++) acc[tt][j] = 0.0f;

#pragma unroll
    for (int kc = 0; kc < 8; kc++) {
        const uint32_t* ah = Ah + kc * 4;
        const uint32_t* al = Al + kc * 4;
#pragma unroll
        for (int tt = 0; tt < 16; tt++) {
            int n  = tt * 8 + qr;
            int w0 = kc * 8 + qc;
            int sx = 4 * (n & 7);
            uint32_t bh0 = smw[n * 64 + (w0 ^ sx)];
            uint32_t bh1 = smw[n * 64 + ((w0 + 4) ^ sx)];
            uint32_t bl0 = smw[8192 + n * 64 + (w0 ^ sx)];
            uint32_t bl1 = smw[8192 + n * 64 + ((w0 + 4) ^ sx)];
            hmma(acc[tt], ah, bh0, bh1);
            hmma(acc[tt], al, bh0, bh1);
            hmma(acc[tt], ah, bl0, bl1);
        }
    }

#pragma unroll
    for (int tt = 0; tt < 16; tt++) {
        int nl = tt * 8 + 2 * qc;                 // col within 128-block
        int n0 = colBase + nl;                    // col in gall row
        float b0 = 0.f, b1 = 0.f;
        if (bias) { b0 = bias[nlBase + nl]; b1 = bias[nlBase + nl + 1]; }
        *reinterpret_cast<float2*>(C + (size_t)r0 * 1536 + n0) =
            make_float2(acc[tt][0] + b0, acc[tt][1] + b1);
        *reinterpret_cast<float2*>(C + (size_t)r1 * 1536 + n0) =
            make_float2(acc[tt][2] + b0, acc[tt][3] + b1);
    }
}

// ============================================================
// Central GRU combine
// ============================================================
__global__ void gru_central(const float* __restrict__ gi, const float* __restrict__ gh,
                            const float* __restrict__ hprev,
                            float* __restrict__ hrnn, float* __restrict__ out_h)
{
    int e = blockIdx.x * 256 + threadIdx.x;
    int row = e >> 7, hh = e & 127;
    size_t base = (size_t)row * G3;
    float r = sigf(gi[base + hh]        + gh[base + hh]);
    float z = sigf(gi[base + 128 + hh]  + gh[base + 128 + hh]);
    float n = tanhf(gi[base + 256 + hh] + r * gh[base + 256 + hh]);
    float hv = (1.0f - z) * n + z * hprev[e];
    hrnn[e]  = hv;
    out_h[e] = hv;
}

// ============================================================
// HMMA persistent bi-GRU recurrence (unchanged from R14 WIN).
// ============================================================
#define BLW 24576            // 384*64 words per buffer
#define RECUR_DYN (2 * BLW * 4)

__global__ __launch_bounds__(256, 1)
void recur_mma(const float* __restrict__ gall,
               const float* __restrict__ Whh_f, const float* __restrict__ bhh_f,
               const float* __restrict__ Whh_b, const float* __restrict__ bhh_b,
               const float* __restrict__ Wc,
               float2* __restrict__ lpf, float2* __restrict__ lpb)
{
    extern __shared__ uint32_t smw[];        // [hi: BLW][lo: BLW]
    __shared__ float sbhh[384];
    __shared__ float swc[256];

    const int tid  = threadIdx.x;
    const int w    = tid >> 5, lane = tid & 31;
    const int qr   = lane >> 2;
    const int qc   = lane & 3;
    const int dir  = blockIdx.y;
    const int tb   = blockIdx.x * 128;
    const int r0   = tb + w * 16 + qr;
    const int r1   = r0 + 8;
    const int bb   = r0 >> 4;
    const int i0   = qr, i1 = qr + 8;
    const int gofs = dir ? 768 : 0;

    const float* Whh = dir ? Whh_b : Whh_f;
    const float* bhh = dir ? bhh_b : bhh_f;
    float2* lp = dir ? lpb : lpf;

    for (int idx = tid; idx < 384 * 64; idx += 256) {
        int n = idx >> 6, ww = idx & 63;
        float2 v = *reinterpret_cast<const float2*>(Whh + (size_t)n * 128 + 2 * ww);
        uint32_t hi, lo; packsplit(v.x, v.y, hi, lo);
        int ws = ww ^ (4 * (n & 7));
        smw[n * 64 + ws]       = hi;
        smw[BLW + n * 64 + ws] = lo;
    }
    for (int q = tid; q < 384; q += 256) sbhh[q] = bhh[q];
    if (tid < 128) {
        swc[tid]       = Wc[dir * 128 + tid];
        swc[128 + tid] = Wc[256 + dir * 128 + tid];
    }
    __syncthreads();

    float hprev[16][4];
#pragma unroll
    for (int T = 0; T < 16; T++)
#pragma unroll
        for (int j = 0; j < 4; j++) hprev[T][j] = 0.0f;

    const float* gs0 = gall + (size_t)r0 * 1536 + gofs;
    const float* gs1 = gall + (size_t)r1 * 1536 + gofs;

    for (int s = 0; s < T_N; s++) {
        const int t = dir ? (T_N - 1 - s) : s;
        const int j0 = t + (t >= i0);
        const int j1 = t + (t >= i1);
        const float* gn0 = gall + (size_t)((bb << 4) | j0) * 1536 + gofs + 384;
        const float* gn1 = gall + (size_t)((bb << 4) | j1) * 1536 + gofs + 384;

        uint32_t Ah[32], Al[32];
#pragma unroll
        for (int kc = 0; kc < 8; kc++) {
#pragma unroll
            for (int half = 0; half < 2; half++) {
                const float* hv = hprev[2 * kc + half];
                packsplit(hv[0], hv[1], Ah[kc * 4 + 2 * half + 0], Al[kc * 4 + 2 * half + 0]);
                packsplit(hv[2], hv[3], Ah[kc * 4 + 2 * half + 1], Al[kc * 4 + 2 * half + 1]);
            }
        }

        float p0r0 = 0.f, p1r0 = 0.f, p0r1 = 0.f, p1r1 = 0.f;

#pragma unroll
        for (int c = 0; c < 4; c++) {
            float acc[3][4][4];
#pragma unroll
            for (int g3 = 0; g3 < 3; g3++)
#pragma unroll
                for (int tt = 0; tt < 4; tt++)
#pragma unroll
                    for (int j = 0; j < 4; j++) acc[g3][tt][j] = 0.0f;

#pragma unroll
            for (int kc = 0; kc < 8; kc++) {
                const uint32_t* ah = Ah + kc * 4;
                const uint32_t* al = Al + kc * 4;
#pragma unroll
                for (int g3 = 0; g3 < 3; g3++) {
#pragma unroll
                    for (int tt = 0; tt < 4; tt++) {
                        int n   = g3 * 128 + c * 32 + tt * 8 + qr;
                        int w0  = kc * 8 + qc;
                        int sx  = 4 * (n & 7);
                        uint32_t bh0 = smw[n * 64 + (w0 ^ sx)];
                        uint32_t bh1 = smw[n * 64 + ((w0 + 4) ^ sx)];
                        uint32_t bl0 = smw[BLW + n * 64 + (w0 ^ sx)];
                        uint32_t bl1 = smw[BLW + n * 64 + ((w0 + 4) ^ sx)];
                        hmma(acc[g3][tt], ah, bh0, bh1);
                        hmma(acc[g3][tt], al, bh0, bh1);
                        hmma(acc[g3][tt], ah, bl0, bl1);
                    }
                }
            }

#pragma unroll
            for (int tt = 0; tt < 4; tt++) {
                int T  = c * 4 + tt;
                int co = T * 8 + 2 * qc;
                float2 sr0 = *reinterpret_cast<const float2*>(gs0 + co);
                float2 nr0 = *reinterpret_cast<const float2*>(gn0 + co);
                float2 sr1 = *reinterpret_cast<const float2*>(gs1 + co);
                float2 nr1 = *reinterpret_cast<const float2*>(gn1 + co);
                float2 sz0 = *reinterpret_cast<const float2*>(gs0 + 128 + co);
                float2 nz0 = *reinterpret_cast<const float2*>(gn0 + 128 + co);
                float2 sz1 = *reinterpret_cast<const float2*>(gs1 + 128 + co);
                float2 nz1 = *reinterpret_cast<const float2*>(gn1 + 128 + co);
                float2 sn0 = *reinterpret_cast<const float2*>(gs0 + 256 + co);
                float2 nn0 = *reinterpret_cast<const float2*>(gn0 + 256 + co);
                float2 sn1 = *reinterpret_cast<const float2*>(gs1 + 256 + co);
                float2 nn1 = *reinterpret_cast<const float2*>(gn1 + 256 + co);

                float gir[4] = { sr0.x + nr0.x, sr0.y + nr0.y, sr1.x + nr1.x, sr1.y + nr1.y };
                float giz[4] = { sz0.x + nz0.x, sz0.y + nz0.y, sz1.x + nz1.x, sz1.y + nz1.y };
                float gin[4] = { sn0.x + nn0.x, sn0.y + nn0.y, sn1.x + nn1.x, sn1.y + nn1.y };

                float hv[4];
#pragma unroll
                for (int j = 0; j < 4; j++) {
                    int col = co + (j & 1);
                    float rr = sigf(gir[j] + acc[0][tt][j] + sbhh[col]);
                    float zz = sigf(giz[j] + acc[1][tt][j] + sbhh[128 + col]);
                    float nn = tanhf(gin[j] + rr * (acc[2][tt][j] + sbhh[256 + col]));
                    float h  = (1.0f - zz) * nn + zz * hprev[T][j];
                    hprev[T][j] = h;
                    hv[j] = h;
                }
                p0r0 = fmaf(hv[0], swc[co], fmaf(hv[1], swc[co + 1], p0r0));
                p1r0 = fmaf(hv[0], swc[128 + co], fmaf(hv[1], swc[128 + co + 1], p1r0));
                p0r1 = fmaf(hv[2], swc[co], fmaf(hv[3], swc[co + 1], p0r1));
                p1r1 = fmaf(hv[2], swc[128 + co], fmaf(hv[3], swc[128 + co + 1], p1r1));
            }
        }

#pragma unroll
        for (int o = 1; o <= 2; o <<= 1) {
            p0r0 += __shfl_xor_sync(0xFFFFFFFFu, p0r0, o);
            p1r0 += __shfl_xor_sync(0xFFFFFFFFu, p1r0, o);
            p0r1 += __shfl_xor_sync(0xFFFFFFFFu, p0r1, o);
            p1r1 += __shfl_xor_sync(0xFFFFFFFFu, p1r1, o);
        }
        if (qc == 0) {
            lp[(size_t)r0 * T_N + t] = make_float2(p0r0, p1r0);
            lp[(size_t)r1 * T_N + t] = make_float2(p0r1, p1r1);
        }
    }
}

// ============================================================
// hard_w from partial logits + gumbel noise
// ============================================================
__global__ void hard_kernel(const float2* __restrict__ lpf, const float2* __restrict__ lpb,
                            const float* __restrict__ bc, const float* __restrict__ gu,
                            float* __restrict__ hard)
{
    int p = blockIdx.x * 256 + threadIdx.x;
    if (p >= BZ * T_N) return;
    float2 f = lpf[p], b = lpb[p];
    float l0 = f.x + b.x + bc[0];
    float l1 = f.y + b.y + bc[1];
    float u0 = gu[2 * (size_t)p], u1 = gu[2 * (size_t)p + 1];
    float g0 = -logf(-logf(u0 + 1e-10f) + 1e-10f);
    float g1 = -logf(-logf(u1 + 1e-10f) + 1e-10f);
    hard[p] = sigf(((l1 + g1) - (l0 + g0)) / TAUF);
}

// ============================================================
// attention scores + softmax + aggregation.  One warp per (b, i) row.
// ============================================================
__global__ void attn_agg(const float* __restrict__ q, const float* __restrict__ k,
                         const float* __restrict__ hard, const float* __restrict__ hrnn,
                         float* __restrict__ agg)
{
    int warp = threadIdx.x >> 5, lane = threadIdx.x & 31;
    int row = blockIdx.x * 8 + warp;
    int b = row >> 4, i = row & 15;

    float sc = -1e30f, hw = 0.f;
    if (lane < 15) {
        int j = lane + (lane >= i);
        int nrow = (b << 4) | j;
        hw = hard[(size_t)row * 15 + lane];
        const float* qr = q + (size_t)row * NA;
        const float* kr = k + (size_t)nrow * NA;
        float dot = 0.f;
#pragma unroll
        for (int d = 0; d < NA; d++) dot += qr[d] * kr[d];
        sc = dot * hw * 0.17677669529663687f;
    }
    float mx = sc;
#pragma unroll
    for (int o = 16; o; o >>= 1) mx = fmaxf(mx, __shfl_xor_sync(0xFFFFFFFFu, mx, o));
    float ev = (lane < 15) ? expf(sc - mx) : 0.f;
    float se = ev;
#pragma unroll
    for (int o = 16; o; o >>= 1) se += __shfl_xor_sync(0xFFFFFFFFu, se, o);
    float wgt = (lane < 15) ? hw * (ev / se) : 0.f;

#pragma unroll
    for (int c = 0; c < 4; c++) {
        float acc = 0.f;
#pragma unroll
        for (int m = 0; m < 15; m++) {
            float wm = __shfl_sync(0xFFFFFFFFu, wgt, m);
            int jm = m + (m >= i);
            acc += wm * hrnn[(size_t)((b << 4) | jm) * H + c * 32 + lane];
        }
        agg[(size_t)row * H + c * 32 + lane] = acc;
    }
}

// ============================================================
// out = [hrnn | agg] @ W2^T + b2
// ============================================================
__global__ void out_kernel(const float* __restrict__ hrnn, const float* __restrict__ agg,
                           const float* __restrict__ W2, const float* __restrict__ b2,
                           float* __restrict__ out)
{
    __shared__ float w2s[NACT * 256];
    int tid = threadIdx.x;
    for (int x = tid; x < NACT * 256; x += 256) w2s[x] = W2[x];
    __syncthreads();

    int g = blockIdx.x * 256 + tid;
    if (g >= BZ * NACT) return;
    int row = g / NACT, n = g % NACT;
    const float* hr = hrnn + (size_t)row * H;
    const float* ag = agg  + (size_t)row * H;
    float acc = b2[n];
#pragma unroll 4
    for (int kk = 0; kk < 128; kk++) acc += hr[kk] * w2s[n * 256 + kk];
#pragma unroll 4
    for (int kk = 0; kk < 128; kk++) acc += ag[kk] * w2s[n * 256 + 128 + kk];
    out[g] = acc;
}

// ============================================================
extern "C" void kernel_launch(void* const* d_in, const int* in_sizes, int n_in,
                              void* d_out, int out_size)
{
    const float* inputs = (const float*)d_in[0];
    const float* hidden = (const float*)d_in[1];
    const float* gu     = (const float*)d_in[2];
    const float* W1     = (const float*)d_in[3];
    const float* b1     = (const float*)d_in[4];
    const float* Wih_c  = (const float*)d_in[5];
    const float* Whh_c  = (const float*)d_in[6];
    const float* bih_c  = (const float*)d_in[7];
    const float* bhh_c  = (const float*)d_in[8];
    const float* Wih_f  = (const float*)d_in[9];
    const float* Whh_f  = (const float*)d_in[10];
    const float* bih_f  = (const float*)d_in[11];
    const float* bhh_f  = (const float*)d_in[12];
    const float* Wih_b  = (const float*)d_in[13];
    const float* Whh_b  = (const float*)d_in[14];
    const float* bih_b  = (const float*)d_in[15];
    const float* bhh_b  = (const float*)d_in[16];
    const float* Wc     = (const float*)d_in[17];
    const float* bc     = (const float*)d_in[18];
    const float* Wq     = (const float*)d_in[19];
    const float* Wk     = (const float*)d_in[20];
    const float* W2     = (const float*)d_in[21];
    const float* b2     = (const float*)d_in[22];

    float* S = nullptr;
    cudaGetSymbolAddress((void**)&S, g_scratch);

    const size_t U = (size_t)BZ * H;
    const size_t V = (size_t)BZ * G3;
    float* x1   = S;
    float* gi   = x1 + U;
    float* gh   = gi + V;
    float* hrnn = gh + V;
    float* gall = hrnn + U;                       // BZ * 1536
    float* lpfb = gall + (size_t)BZ * 1536;
    float2* lpf = (float2*)lpfb;
    float2* lpb = lpf + (size_t)BZ * T_N;
    float* hard = (float*)(lpb + (size_t)BZ * T_N);
    float* qv   = hard + (size_t)BZ * T_N;
    float* kv   = qv + (size_t)BZ * NA;
    float* agg  = kv + (size_t)BZ * NA;

    float* out   = (float*)d_out;
    float* out_h = out + (size_t)BZ * NACT;

    cudaFuncSetAttribute(recur_mma,
                         cudaFuncAttributeMaxDynamicSharedMemorySize, RECUR_DYN);
    cudaFuncSetAttribute(hgemm<0>,
                         cudaFuncAttributeMaxDynamicSharedMemorySize, HSMEM);
    cudaFuncSetAttribute(hgemm<1>,
                         cudaFuncAttributeMaxDynamicSharedMemorySize, HSMEM);
    cudaFuncSetAttribute(hgemm<2>,
                         cudaFuncAttributeMaxDynamicSharedMemorySize, HSMEM);
    cudaFuncSetAttribute(hgemm_ih,
                         cudaFuncAttributeMaxDynamicSharedMemorySize, HSMEM);

    dim3 blk(256);

    // x1 = relu(inputs @ W1^T + b1)
    hgemm<2><<<dim3(1, BZ/128), blk, HSMEM>>>(inputs, IN_D, W1, IN_D, 0, b1, x1, 128, 128);
    // central GRU gates
    hgemm<1><<<dim3(3, BZ/128), blk, HSMEM>>>(x1,     H, Wih_c, H, 0, bih_c, gi, G3, G3);
    hgemm<1><<<dim3(3, BZ/128), blk, HSMEM>>>(hidden, H, Whh_c, H, 0, bhh_c, gh, G3, G3);
    gru_central<<<BZ * H / 256, blk>>>(gi, gh, hidden, hrnn, out_h);

    // packed input-gate precompute [gsf|gnf|gsb|gnb]
    hgemm_ih<<<dim3(12, BZ/128), blk, HSMEM>>>(hrnn, Wih_f, bih_f, Wih_b, bih_b, gall);

    // q, k projections
    hgemm<0><<<dim3(1, BZ/128), blk, HSMEM>>>(hrnn, H, Wq, H, 0, nullptr, qv, NA, NA);
    hgemm<0><<<dim3(1, BZ/128), blk, HSMEM>>>(hrnn, H, Wk, H, 0, nullptr, kv, NA, NA);

    // HMMA persistent bi-GRU recurrence
    recur_mma<<<dim3(BZ/128, 2), blk, RECUR_DYN>>>(gall, Whh_f, bhh_f, Whh_b, bhh_b,
                                                   Wc, lpf, lpb);

    // gumbel hard weights
    hard_kernel<<<(BZ * T_N + 255) / 256, blk>>>(lpf, lpb, bc, gu, hard);

    // attention + aggregation
    attn_agg<<<BZ / 8, blk>>>(qv, kv, hard, hrnn, agg);

    // output head
    out_kernel<<<(BZ * NACT + 255) / 256, blk>>>(hrnn, agg, W2, b2, out);
}